// round 13
// baseline (speedup 1.0000x reference)
#include <cuda_runtime.h>
#include <cuda_bf16.h>
#include <cuda_fp16.h>
#include <cstdint>
#include <cstddef>
#include <type_traits>

// ---------------------------------------------------------------------------
// SpatialSelfAttention on GB300 — bf16 mma.sync.m16n8k16 engine.
// R13: 16 warps / 512 threads per 128x128 tile (4m x 4n warp grid, 32x32 per
// warp). Halves per-thread accumulator state (~80 regs) -> 4 warps/SMSP for
// latency hiding, still 1 CTA/SM. Softmax fused into GEMM epilogues (R12).
// ---------------------------------------------------------------------------

namespace {
constexpr int kB = 8;
constexpr int kC = 512;
constexpr int kN = 4096;
constexpr int kG = 32;
constexpr int kCPG = kC / kG;
constexpr size_t kCN = (size_t)kC * kN;
constexpr size_t kNN = (size_t)kN * kN;
constexpr int kStages = 3;
constexpr int kSmemBytes = kStages * 32768;   // 96 KB
constexpr int kThreads = 512;
}

// Scratch
__device__ __nv_bfloat16  g_hnT[kB * kCN];                 // [n][c]
__device__ __nv_bfloat16  g_qk [kB * (size_t)kN * 1024];   // q|k  [n][1024]
__device__ __nv_bfloat16  g_v  [kB * kCN];                 // [c][n]
__device__ __nv_bfloat16  g_oT [kB * kCN];                 // [n][c]
__device__ __nv_bfloat16  g_s  [kB * kNN];                 // unnormalized probs
__device__ __nv_bfloat16  g_wr [4 * kC * kC];              // wq|wk|wv|wo
__device__ float          g_bqk[1024];
__device__ float2         g_stats[kB * kG];                // (mean, rsqrt(var+eps))
__device__ float          g_rowsum[kB * kN];               // softmax denominators

// ---------------------------------------------------------------------------
__device__ __forceinline__ uint32_t smem_u32(const void* p) {
    uint32_t a;
    asm("{ .reg .u64 t; cvta.to.shared.u64 t, %1; cvt.u32.u64 %0, t; }"
        : "=r"(a) : "l"(p));
    return a;
}
__device__ __forceinline__ void cp_async16(uint32_t dst, const void* src) {
    asm volatile("cp.async.cg.shared.global [%0], [%1], 16;"
                 :: "r"(dst), "l"(src));
}
__device__ __forceinline__ void ldsm_x4(uint32_t* r, uint32_t addr) {
    asm volatile("ldmatrix.sync.aligned.m8n8.x4.shared.b16 {%0,%1,%2,%3}, [%4];"
                 : "=r"(r[0]), "=r"(r[1]), "=r"(r[2]), "=r"(r[3]) : "r"(addr));
}
__device__ __forceinline__ void mma_bf16(float* d, const uint32_t* a,
                                         const uint32_t* b) {
    asm volatile(
        "mma.sync.aligned.m16n8k16.row.col.f32.bf16.bf16.f32 "
        "{%0,%1,%2,%3}, {%4,%5,%6,%7}, {%8,%9}, {%0,%1,%2,%3};"
        : "+f"(d[0]), "+f"(d[1]), "+f"(d[2]), "+f"(d[3])
        : "r"(a[0]), "r"(a[1]), "r"(a[2]), "r"(a[3]), "r"(b[0]), "r"(b[1]));
}

// ---------------------------------------------------------------------------
// bf16 GEMM: D[m,n] = alpha * sum_k A[m,k]*B[n,k] (+bias)(+resid)
// EXP2:  epilogue stores exp2(alpha*acc) bf16 + atomic per-row sums.
// NORM_M: epilogue scales row m by 1/rowsum[m].
// A: K-major [M,K]; B: K-major [N,K]; C row-major [M,ldc] OutT.
// 128x128x64 tiles, 3-stage cp.async pipeline, 16 warps (4m x 4n, 32x32 ea).
// ---------------------------------------------------------------------------
template <typename OutT, bool BIAS_N, bool BIAS_M, bool RESID,
          bool EXP2, bool NORM_M>
__global__ __launch_bounds__(kThreads)
void mma_gemm(const __nv_bfloat16* __restrict__ A, int lda, size_t sA,
              const __nv_bfloat16* __restrict__ B, int ldb, size_t sB,
              OutT* __restrict__ C, int ldc, size_t sC,
              int K, float alpha,
              const float* __restrict__ bias,
              const float* __restrict__ resid, size_t sR,
              float* __restrict__ rowsum, size_t sRS)
{
    extern __shared__ char smem[];
    const uint32_t base = smem_u32(smem);

    const int tid = threadIdx.x;
    const int wid = tid >> 5;
    const int l   = tid & 31;
    const int wm  = wid & 3;       // 4 warps along M (32 rows each)
    const int wn  = wid >> 2;      // 4 warps along N (32 cols each)

    A += (size_t)blockIdx.z * sA;
    B += (size_t)blockIdx.z * sB;
    C += (size_t)blockIdx.z * sC;
    if (RESID) resid += (size_t)blockIdx.z * sR;
    if (EXP2 || NORM_M) rowsum += (size_t)blockIdx.z * sRS;

    const int bm = blockIdx.y * 128;
    const int bn = blockIdx.x * 128;

    const int rowA = (l & 7) + ((l >> 3) & 1) * 8;
    const int jA   = (l >> 4) & 1;
    const int rowB = (l & 7) + ((l >> 4) & 1) * 8;
    const int jB   = (l >> 3) & 1;

    float acc[2][4][4];
    #pragma unroll
    for (int i = 0; i < 2; i++)
        #pragma unroll
        for (int j = 0; j < 4; j++)
            #pragma unroll
            for (int r = 0; r < 4; r++) acc[i][j][r] = 0.f;

    const int nk = K >> 6;   // BK = 64 bf16; nk >= 2 for all calls here

    auto load_tile = [&](int it, int s) {
        const uint32_t aB = base + s * 32768;
        const uint32_t bB = aB + 16384;
        const __nv_bfloat16* ag = A + (size_t)bm * lda + (it << 6);
        const __nv_bfloat16* bg = B + (size_t)bn * ldb + (it << 6);
        #pragma unroll
        for (int i = 0; i < 2; ++i) {
            const int idx = tid + (i << 9);        // 0..1023
            const int r = idx >> 3, c = idx & 7;
            const uint32_t so = (uint32_t)(r * 128 + ((c ^ (r & 7)) << 4));
            cp_async16(aB + so, ag + (size_t)r * lda + c * 8);
            cp_async16(bB + so, bg + (size_t)r * ldb + c * 8);
        }
        asm volatile("cp.async.commit_group;" ::: "memory");
    };

    load_tile(0, 0);
    load_tile(1, 1);

    for (int it = 0; it < nk; ++it) {
        if (it + 1 < nk) {
            asm volatile("cp.async.wait_group 1;" ::: "memory");
        } else {
            asm volatile("cp.async.wait_group 0;" ::: "memory");
        }
        // Single barrier: proves all warps finished consuming stage
        // (it-1)%3 == (it+2)%3, which the prefetch below overwrites.
        __syncthreads();
        if (it + 2 < nk) load_tile(it + 2, (it + 2) % kStages);

        const uint32_t aB = base + (it % kStages) * 32768;
        const uint32_t bB = aB + 16384;

        #pragma unroll
        for (int ks = 0; ks < 4; ++ks) {
            uint32_t afr[2][4];
            #pragma unroll
            for (int fm = 0; fm < 2; ++fm) {
                const int row = wm * 32 + fm * 16 + rowA;
                const int ch  = (2 * ks + jA) ^ (row & 7);
                ldsm_x4(afr[fm], aB + (uint32_t)(row * 128 + (ch << 4)));
            }
            uint32_t bfr[4][2];
            #pragma unroll
            for (int f2 = 0; f2 < 2; ++f2) {
                const int row = wn * 32 + f2 * 16 + rowB;
                const int ch  = (2 * ks + jB) ^ (row & 7);
                uint32_t t[4];
                ldsm_x4(t, bB + (uint32_t)(row * 128 + (ch << 4)));
                bfr[f2 * 2][0]     = t[0]; bfr[f2 * 2][1]     = t[1];
                bfr[f2 * 2 + 1][0] = t[2]; bfr[f2 * 2 + 1][1] = t[3];
            }
            #pragma unroll
            for (int fm = 0; fm < 2; ++fm)
                #pragma unroll
                for (int fn = 0; fn < 4; ++fn)
                    mma_bf16(acc[fm][fn], afr[fm], bfr[fn]);
        }
    }

    if constexpr (EXP2) {
        // Unnormalized softmax probs + per-row partial sums.
        #pragma unroll
        for (int fm = 0; fm < 2; ++fm) {
            const int r0 = bm + wm * 32 + fm * 16 + (l >> 2);
            #pragma unroll
            for (int half = 0; half < 2; ++half) {
                const int m = r0 + half * 8;
                float rsum = 0.f;
                #pragma unroll
                for (int fn = 0; fn < 4; ++fn) {
                    const int col = bn + wn * 32 + fn * 8 + (l & 3) * 2;
                    const float p0 = exp2f(acc[fm][fn][half * 2 + 0] * alpha);
                    const float p1 = exp2f(acc[fm][fn][half * 2 + 1] * alpha);
                    *reinterpret_cast<__nv_bfloat162*>(
                        &C[(size_t)m * ldc + col]) = __floats2bfloat162_rn(p0, p1);
                    rsum += p0 + p1;
                }
                rsum += __shfl_xor_sync(0xffffffffu, rsum, 1);
                rsum += __shfl_xor_sync(0xffffffffu, rsum, 2);
                if ((l & 3) == 0) atomicAdd(&rowsum[m], rsum);
            }
        }
    } else {
        #pragma unroll
        for (int fm = 0; fm < 2; ++fm) {
            const int r0 = bm + wm * 32 + fm * 16 + (l >> 2);
            #pragma unroll
            for (int half = 0; half < 2; ++half) {
                const int m = r0 + half * 8;
                const float bmv = BIAS_M ? bias[m] : 0.f;
                const float rinv = NORM_M ? (1.f / rowsum[m]) : 1.f;
                #pragma unroll
                for (int fn = 0; fn < 4; ++fn) {
                    const int col = bn + wn * 32 + fn * 8 + (l & 3) * 2;
                    float2 o;
                    o.x = acc[fm][fn][half * 2 + 0] * alpha;
                    o.y = acc[fm][fn][half * 2 + 1] * alpha;
                    if (NORM_M) { o.x *= rinv; o.y *= rinv; }
                    if (BIAS_N) { o.x += bias[col]; o.y += bias[col + 1]; }
                    if (BIAS_M) { o.x += bmv; o.y += bmv; }
                    if (RESID) {
                        const float2 rv = *reinterpret_cast<const float2*>(
                            &resid[(size_t)m * ldc + col]);
                        o.x += rv.x; o.y += rv.y;
                    }
                    OutT* dst = &C[(size_t)m * ldc + col];
                    if constexpr (std::is_same_v<OutT, float>) {
                        *reinterpret_cast<float2*>(dst) = o;
                    } else {
                        *reinterpret_cast<__nv_bfloat162*>(dst) =
                            __floats2bfloat162_rn(o.x, o.y);
                    }
                }
            }
        }
    }
}

// ---------------------------------------------------------------------------
// GroupNorm stats: one block per (batch, group) -> (mean, rsqrt(var+eps))
// ---------------------------------------------------------------------------
__global__ __launch_bounds__(256) void gn_stats_kernel(const float* __restrict__ x,
                                                       float2* __restrict__ stats) {
    const int b = blockIdx.x / kG;
    const int g = blockIdx.x % kG;
    const size_t base = (size_t)b * kCN + (size_t)g * kCPG * kN;
    const float4* x4 = reinterpret_cast<const float4*>(x + base);
    const int nvec = kCPG * kN / 4;

    float s = 0.f, ss = 0.f;
    for (int i = threadIdx.x; i < nvec; i += 256) {
        float4 v = x4[i];
        s  += v.x + v.y + v.z + v.w;
        ss += v.x * v.x + v.y * v.y + v.z * v.z + v.w * v.w;
    }
    __shared__ float smS[8], smSS[8];
    #pragma unroll
    for (int o = 16; o > 0; o >>= 1) {
        s  += __shfl_xor_sync(0xffffffffu, s, o);
        ss += __shfl_xor_sync(0xffffffffu, ss, o);
    }
    if ((threadIdx.x & 31) == 0) { smS[threadIdx.x >> 5] = s; smSS[threadIdx.x >> 5] = ss; }
    __syncthreads();
    if (threadIdx.x == 0) {
        float S = 0.f, SS = 0.f;
        #pragma unroll
        for (int i = 0; i < 8; i++) { S += smS[i]; SS += smSS[i]; }
        const float invn = 1.f / (float)(kCPG * kN);
        const float mean = S * invn;
        const float var  = SS * invn - mean * mean;
        stats[blockIdx.x] = make_float2(mean, rsqrtf(var + 1e-6f));
    }
}

// ---------------------------------------------------------------------------
// Fused normalize + transpose: x [c][n] fp32 -> hnT [n][c] bf16
// ---------------------------------------------------------------------------
__global__ __launch_bounds__(256) void transnorm_kernel(
    const float* __restrict__ x, const float2* __restrict__ stats,
    const float* __restrict__ scale, const float* __restrict__ bias,
    __nv_bfloat16* __restrict__ dst)
{
    __shared__ float t[32][33];
    const int bz = blockIdx.z;
    const size_t boff = (size_t)bz * kCN;
    const int n0 = blockIdx.x * 32, c0 = blockIdx.y * 32;
    const int tx = threadIdx.x & 31, ty = threadIdx.x >> 5;
    #pragma unroll
    for (int i = 0; i < 4; i++)
        t[ty + i * 8][tx] = x[boff + (size_t)(c0 + ty + i * 8) * kN + n0 + tx];
    __syncthreads();
    const int c = c0 + tx;
    const float2 st = stats[bz * kG + (c >> 4)];
    const float sc = scale[c] * st.y;
    const float bi = bias[c] - st.x * sc;
    #pragma unroll
    for (int i = 0; i < 4; i++)
        dst[boff + (size_t)(n0 + ty + i * 8) * kC + c] =
            __float2bfloat16_rn(t[tx][ty + i * 8] * sc + bi);
}

// ---------------------------------------------------------------------------
// Merged setup: weight cvt (1M elems) + bias concat + rowsum zero, one launch.
// ---------------------------------------------------------------------------
__global__ __launch_bounds__(256) void setup_kernel(
    const float* __restrict__ wq, const float* __restrict__ wk,
    const float* __restrict__ wv, const float* __restrict__ wo,
    __nv_bfloat16* __restrict__ wdst,
    const float* __restrict__ bq, const float* __restrict__ bk,
    float* __restrict__ bqk, float* __restrict__ rowsum)
{
    const int i = blockIdx.x * 256 + threadIdx.x;     // < 1048576
    const int sel = i >> 18;
    const int off = i & 0x3FFFF;
    const float* src = (sel == 0) ? wq : (sel == 1) ? wk : (sel == 2) ? wv : wo;
    wdst[i] = __float2bfloat16_rn(src[off]);
    if (i < 1024) bqk[i] = (i < 512) ? bq[i] : bk[i - 512];
    if (i < kB * kN) rowsum[i] = 0.f;
}

// ---------------------------------------------------------------------------
extern "C" void kernel_launch(void* const* d_in, const int* in_sizes, int n_in,
                              void* d_out, int out_size) {
    const float* x  = (const float*)d_in[0];
    const float* gs = (const float*)d_in[1];
    const float* gb = (const float*)d_in[2];
    const float* wq = (const float*)d_in[3];
    const float* bq = (const float*)d_in[4];
    const float* wk = (const float*)d_in[5];
    const float* bk = (const float*)d_in[6];
    const float* wv = (const float*)d_in[7];
    const float* bv = (const float*)d_in[8];
    const float* wo = (const float*)d_in[9];
    const float* bo = (const float*)d_in[10];
    float* out = (float*)d_out;

    __nv_bfloat16 *hnT, *qkb, *v, *oT, *probs, *wr;
    float *bqk, *rowsum;
    float2* stats;
    cudaGetSymbolAddress((void**)&hnT,    g_hnT);
    cudaGetSymbolAddress((void**)&qkb,    g_qk);
    cudaGetSymbolAddress((void**)&v,      g_v);
    cudaGetSymbolAddress((void**)&oT,     g_oT);
    cudaGetSymbolAddress((void**)&probs,  g_s);
    cudaGetSymbolAddress((void**)&wr,     g_wr);
    cudaGetSymbolAddress((void**)&bqk,    g_bqk);
    cudaGetSymbolAddress((void**)&stats,  g_stats);
    cudaGetSymbolAddress((void**)&rowsum, g_rowsum);
    __nv_bfloat16* wvr = wr + 2 * (size_t)kC * kC;
    __nv_bfloat16* wor = wr + 3 * (size_t)kC * kC;

    cudaFuncSetAttribute(
        (const void*)mma_gemm<__nv_bfloat16, true,  false, false, false, false>,
        cudaFuncAttributeMaxDynamicSharedMemorySize, kSmemBytes);
    cudaFuncSetAttribute(
        (const void*)mma_gemm<__nv_bfloat16, false, true,  false, false, false>,
        cudaFuncAttributeMaxDynamicSharedMemorySize, kSmemBytes);
    cudaFuncSetAttribute(
        (const void*)mma_gemm<__nv_bfloat16, false, false, false, true,  false>,
        cudaFuncAttributeMaxDynamicSharedMemorySize, kSmemBytes);
    cudaFuncSetAttribute(
        (const void*)mma_gemm<__nv_bfloat16, false, false, false, false, true>,
        cudaFuncAttributeMaxDynamicSharedMemorySize, kSmemBytes);
    cudaFuncSetAttribute(
        (const void*)mma_gemm<float,         false, true,  true,  false, false>,
        cudaFuncAttributeMaxDynamicSharedMemorySize, kSmemBytes);

    setup_kernel<<<4096, 256>>>(wq, wk, wv, wo, wr, bq, bk, bqk, rowsum);
    gn_stats_kernel<<<kB * kG, 256>>>(x, stats);
    transnorm_kernel<<<dim3(kN / 32, kC / 32, kB), 256>>>(x, stats, gs, gb, hnT);

    // Fused Q|K projection: [4096, 1024] = hn_T @ [wq;wk]^T + [bq;bk]
    const dim3 gQKp(1024 / 128, kN / 128, kB);
    mma_gemm<__nv_bfloat16, true, false, false, false, false>
        <<<gQKp, kThreads, kSmemBytes>>>(
        hnT, kC, kCN, wr, kC, 0, qkb, 1024, (size_t)kN * 1024,
        kC, 1.f, bqk, nullptr, 0, nullptr, 0);

    // V: [c, spatial]
    const dim3 gV(kN / 128, kC / 128, kB);
    mma_gemm<__nv_bfloat16, false, true, false, false, false>
        <<<gV, kThreads, kSmemBytes>>>(
        wvr, kC, 0, hnT, kC, kCN, v, kN, kCN, kC, 1.f, bv, nullptr, 0,
        nullptr, 0);

    // probs[i,j] = exp2((q.k) * log2e / sqrt(C)) -> bf16, rowsum += partials
    const dim3 gS(kN / 128, kN / 128, kB);
    mma_gemm<__nv_bfloat16, false, false, false, true, false>
        <<<gS, kThreads, kSmemBytes>>>(
        qkb, 1024, (size_t)kN * 1024, qkb + 512, 1024, (size_t)kN * 1024,
        probs, kN, kNN, kC,
        0.044194173824159216f * 1.4426950408889634f, nullptr, nullptr, 0,
        rowsum, kN);

    // oT[i,c] = (sum_j P[i,j] * v[c,j]) / rowsum[i]
    const dim3 gO(kC / 128, kN / 128, kB);
    mma_gemm<__nv_bfloat16, false, false, false, false, true>
        <<<gO, kThreads, kSmemBytes>>>(
        probs, kN, kNN, v, kN, kCN, oT, kC, kCN, kN, 1.f, nullptr, nullptr, 0,
        rowsum, kN);

    // out = W_o @ oT^T + bo + x
    mma_gemm<float, false, true, true, false, false>
        <<<gV, kThreads, kSmemBytes>>>(
        wor, kC, 0, oT, kC, kCN, out, kN, kCN, kC, 1.f, bo, x, kCN,
        nullptr, 0);
}

// round 16
// speedup vs baseline: 1.2406x; 1.2406x over previous
#include <cuda_runtime.h>
#include <cuda_bf16.h>
#include <cuda_fp16.h>
#include <cstdint>
#include <cstddef>
#include <type_traits>

// ---------------------------------------------------------------------------
// SpatialSelfAttention on GB300 — bf16 mma.sync.m16n8k16 engine.
// R15 (= R14 resubmitted after infra failure): R12 engine (8 warps, 32x64 per
// warp), merged setup kernel, softmax fused into GEMM epilogues
// (exp2 + atomic rowsum; normalize in attnV epilogue).
// ---------------------------------------------------------------------------

namespace {
constexpr int kB = 8;
constexpr int kC = 512;
constexpr int kN = 4096;
constexpr int kG = 32;
constexpr int kCPG = kC / kG;
constexpr size_t kCN = (size_t)kC * kN;
constexpr size_t kNN = (size_t)kN * kN;
constexpr int kStages = 3;
constexpr int kSmemBytes = kStages * 32768;   // 96 KB
}

// Scratch
__device__ __nv_bfloat16  g_hnT[kB * kCN];                 // [n][c]
__device__ __nv_bfloat16  g_qk [kB * (size_t)kN * 1024];   // q|k  [n][1024]
__device__ __nv_bfloat16  g_v  [kB * kCN];                 // [c][n]
__device__ __nv_bfloat16  g_oT [kB * kCN];                 // [n][c]
__device__ __nv_bfloat16  g_s  [kB * kNN];                 // unnormalized probs
__device__ __nv_bfloat16  g_wr [4 * kC * kC];              // wq|wk|wv|wo
__device__ float          g_bqk[1024];
__device__ float2         g_stats[kB * kG];                // (mean, rsqrt(var+eps))
__device__ float          g_rowsum[kB * kN];               // softmax denominators

// ---------------------------------------------------------------------------
__device__ __forceinline__ uint32_t smem_u32(const void* p) {
    uint32_t a;
    asm("{ .reg .u64 t; cvta.to.shared.u64 t, %1; cvt.u32.u64 %0, t; }"
        : "=r"(a) : "l"(p));
    return a;
}
__device__ __forceinline__ void cp_async16(uint32_t dst, const void* src) {
    asm volatile("cp.async.cg.shared.global [%0], [%1], 16;"
                 :: "r"(dst), "l"(src));
}
__device__ __forceinline__ void ldsm_x4(uint32_t* r, uint32_t addr) {
    asm volatile("ldmatrix.sync.aligned.m8n8.x4.shared.b16 {%0,%1,%2,%3}, [%4];"
                 : "=r"(r[0]), "=r"(r[1]), "=r"(r[2]), "=r"(r[3]) : "r"(addr));
}
__device__ __forceinline__ void mma_bf16(float* d, const uint32_t* a,
                                         const uint32_t* b) {
    asm volatile(
        "mma.sync.aligned.m16n8k16.row.col.f32.bf16.bf16.f32 "
        "{%0,%1,%2,%3}, {%4,%5,%6,%7}, {%8,%9}, {%0,%1,%2,%3};"
        : "+f"(d[0]), "+f"(d[1]), "+f"(d[2]), "+f"(d[3])
        : "r"(a[0]), "r"(a[1]), "r"(a[2]), "r"(a[3]), "r"(b[0]), "r"(b[1]));
}

// ---------------------------------------------------------------------------
// bf16 GEMM: D[m,n] = alpha * sum_k A[m,k]*B[n,k] (+bias)(+resid)
// EXP2:  epilogue stores exp2(alpha*acc) bf16 + atomic per-row sums.
// NORM_M: epilogue scales row m by 1/rowsum[m].
// A: K-major [M,K]; B: K-major [N,K]; C row-major [M,ldc] OutT.
// 128x128x64 tiles, 3-stage cp.async pipeline (1 barrier/iter),
// 8 warps (4m x 2n), 32x64 output per warp.
// ---------------------------------------------------------------------------
template <typename OutT, bool BIAS_N, bool BIAS_M, bool RESID,
          bool EXP2, bool NORM_M>
__global__ __launch_bounds__(256)
void mma_gemm(const __nv_bfloat16* __restrict__ A, int lda, size_t sA,
              const __nv_bfloat16* __restrict__ B, int ldb, size_t sB,
              OutT* __restrict__ C, int ldc, size_t sC,
              int K, float alpha,
              const float* __restrict__ bias,
              const float* __restrict__ resid, size_t sR,
              float* __restrict__ rowsum, size_t sRS)
{
    extern __shared__ char smem[];
    const uint32_t base = smem_u32(smem);

    const int tid = threadIdx.x;
    const int wid = tid >> 5;
    const int l   = tid & 31;
    const int wm  = wid & 3;
    const int wn  = wid >> 2;

    A += (size_t)blockIdx.z * sA;
    B += (size_t)blockIdx.z * sB;
    C += (size_t)blockIdx.z * sC;
    if (RESID) resid += (size_t)blockIdx.z * sR;
    if (EXP2 || NORM_M) rowsum += (size_t)blockIdx.z * sRS;

    const int bm = blockIdx.y * 128;
    const int bn = blockIdx.x * 128;

    const int rowA = (l & 7) + ((l >> 3) & 1) * 8;
    const int jA   = (l >> 4) & 1;
    const int rowB = (l & 7) + ((l >> 4) & 1) * 8;
    const int jB   = (l >> 3) & 1;

    float acc[2][8][4];
    #pragma unroll
    for (int i = 0; i < 2; i++)
        #pragma unroll
        for (int j = 0; j < 8; j++)
            #pragma unroll
            for (int r = 0; r < 4; r++) acc[i][j][r] = 0.f;

    const int nk = K >> 6;   // BK = 64 bf16; nk >= 2 for all calls here

    auto load_tile = [&](int it, int s) {
        const uint32_t aB = base + s * 32768;
        const uint32_t bB = aB + 16384;
        const __nv_bfloat16* ag = A + (size_t)bm * lda + (it << 6);
        const __nv_bfloat16* bg = B + (size_t)bn * ldb + (it << 6);
        #pragma unroll
        for (int i = 0; i < 4; ++i) {
            const int idx = tid + (i << 8);
            const int r = idx >> 3, c = idx & 7;
            const uint32_t so = (uint32_t)(r * 128 + ((c ^ (r & 7)) << 4));
            cp_async16(aB + so, ag + (size_t)r * lda + c * 8);
            cp_async16(bB + so, bg + (size_t)r * ldb + c * 8);
        }
        asm volatile("cp.async.commit_group;" ::: "memory");
    };

    load_tile(0, 0);
    load_tile(1, 1);

    for (int it = 0; it < nk; ++it) {
        if (it + 1 < nk) {
            asm volatile("cp.async.wait_group 1;" ::: "memory");
        } else {
            asm volatile("cp.async.wait_group 0;" ::: "memory");
        }
        // Single barrier: proves all warps finished consuming stage
        // (it-1)%3 == (it+2)%3, which the prefetch below overwrites.
        __syncthreads();
        if (it + 2 < nk) load_tile(it + 2, (it + 2) % kStages);

        const uint32_t aB = base + (it % kStages) * 32768;
        const uint32_t bB = aB + 16384;

        #pragma unroll
        for (int ks = 0; ks < 4; ++ks) {
            uint32_t afr[2][4];
            #pragma unroll
            for (int fm = 0; fm < 2; ++fm) {
                const int row = wm * 32 + fm * 16 + rowA;
                const int ch  = (2 * ks + jA) ^ (row & 7);
                ldsm_x4(afr[fm], aB + (uint32_t)(row * 128 + (ch << 4)));
            }
            uint32_t bfr[8][2];
            #pragma unroll
            for (int f2 = 0; f2 < 4; ++f2) {
                const int row = wn * 64 + f2 * 16 + rowB;
                const int ch  = (2 * ks + jB) ^ (row & 7);
                uint32_t t[4];
                ldsm_x4(t, bB + (uint32_t)(row * 128 + (ch << 4)));
                bfr[f2 * 2][0]     = t[0]; bfr[f2 * 2][1]     = t[1];
                bfr[f2 * 2 + 1][0] = t[2]; bfr[f2 * 2 + 1][1] = t[3];
            }
            #pragma unroll
            for (int fm = 0; fm < 2; ++fm)
                #pragma unroll
                for (int fn = 0; fn < 8; ++fn)
                    mma_bf16(acc[fm][fn], afr[fm], bfr[fn]);
        }
    }

    if constexpr (EXP2) {
        // Unnormalized softmax probs + per-row partial sums.
        #pragma unroll
        for (int fm = 0; fm < 2; ++fm) {
            const int r0 = bm + wm * 32 + fm * 16 + (l >> 2);
            #pragma unroll
            for (int half = 0; half < 2; ++half) {
                const int m = r0 + half * 8;
                float rsum = 0.f;
                #pragma unroll
                for (int fn = 0; fn < 8; ++fn) {
                    const int col = bn + wn * 64 + fn * 8 + (l & 3) * 2;
                    const float p0 = exp2f(acc[fm][fn][half * 2 + 0] * alpha);
                    const float p1 = exp2f(acc[fm][fn][half * 2 + 1] * alpha);
                    *reinterpret_cast<__nv_bfloat162*>(
                        &C[(size_t)m * ldc + col]) = __floats2bfloat162_rn(p0, p1);
                    rsum += p0 + p1;
                }
                rsum += __shfl_xor_sync(0xffffffffu, rsum, 1);
                rsum += __shfl_xor_sync(0xffffffffu, rsum, 2);
                if ((l & 3) == 0) atomicAdd(&rowsum[m], rsum);
            }
        }
    } else {
        #pragma unroll
        for (int fm = 0; fm < 2; ++fm) {
            const int r0 = bm + wm * 32 + fm * 16 + (l >> 2);
            #pragma unroll
            for (int half = 0; half < 2; ++half) {
                const int m = r0 + half * 8;
                const float bmv = BIAS_M ? bias[m] : 0.f;
                const float rinv = NORM_M ? (1.f / rowsum[m]) : 1.f;
                #pragma unroll
                for (int fn = 0; fn < 8; ++fn) {
                    const int col = bn + wn * 64 + fn * 8 + (l & 3) * 2;
                    float2 o;
                    o.x = acc[fm][fn][half * 2 + 0] * alpha;
                    o.y = acc[fm][fn][half * 2 + 1] * alpha;
                    if (NORM_M) { o.x *= rinv; o.y *= rinv; }
                    if (BIAS_N) { o.x += bias[col]; o.y += bias[col + 1]; }
                    if (BIAS_M) { o.x += bmv; o.y += bmv; }
                    if (RESID) {
                        const float2 rv = *reinterpret_cast<const float2*>(
                            &resid[(size_t)m * ldc + col]);
                        o.x += rv.x; o.y += rv.y;
                    }
                    OutT* dst = &C[(size_t)m * ldc + col];
                    if constexpr (std::is_same_v<OutT, float>) {
                        *reinterpret_cast<float2*>(dst) = o;
                    } else {
                        *reinterpret_cast<__nv_bfloat162*>(dst) =
                            __floats2bfloat162_rn(o.x, o.y);
                    }
                }
            }
        }
    }
}

// ---------------------------------------------------------------------------
// GroupNorm stats: one block per (batch, group) -> (mean, rsqrt(var+eps))
// ---------------------------------------------------------------------------
__global__ __launch_bounds__(256) void gn_stats_kernel(const float* __restrict__ x,
                                                       float2* __restrict__ stats) {
    const int b = blockIdx.x / kG;
    const int g = blockIdx.x % kG;
    const size_t base = (size_t)b * kCN + (size_t)g * kCPG * kN;
    const float4* x4 = reinterpret_cast<const float4*>(x + base);
    const int nvec = kCPG * kN / 4;

    float s = 0.f, ss = 0.f;
    for (int i = threadIdx.x; i < nvec; i += 256) {
        float4 v = x4[i];
        s  += v.x + v.y + v.z + v.w;
        ss += v.x * v.x + v.y * v.y + v.z * v.z + v.w * v.w;
    }
    __shared__ float smS[8], smSS[8];
    #pragma unroll
    for (int o = 16; o > 0; o >>= 1) {
        s  += __shfl_xor_sync(0xffffffffu, s, o);
        ss += __shfl_xor_sync(0xffffffffu, ss, o);
    }
    if ((threadIdx.x & 31) == 0) { smS[threadIdx.x >> 5] = s; smSS[threadIdx.x >> 5] = ss; }
    __syncthreads();
    if (threadIdx.x == 0) {
        float S = 0.f, SS = 0.f;
        #pragma unroll
        for (int i = 0; i < 8; i++) { S += smS[i]; SS += smSS[i]; }
        const float invn = 1.f / (float)(kCPG * kN);
        const float mean = S * invn;
        const float var  = SS * invn - mean * mean;
        stats[blockIdx.x] = make_float2(mean, rsqrtf(var + 1e-6f));
    }
}

// ---------------------------------------------------------------------------
// Fused normalize + transpose: x [c][n] fp32 -> hnT [n][c] bf16
// ---------------------------------------------------------------------------
__global__ __launch_bounds__(256) void transnorm_kernel(
    const float* __restrict__ x, const float2* __restrict__ stats,
    const float* __restrict__ scale, const float* __restrict__ bias,
    __nv_bfloat16* __restrict__ dst)
{
    __shared__ float t[32][33];
    const int bz = blockIdx.z;
    const size_t boff = (size_t)bz * kCN;
    const int n0 = blockIdx.x * 32, c0 = blockIdx.y * 32;
    const int tx = threadIdx.x & 31, ty = threadIdx.x >> 5;
    #pragma unroll
    for (int i = 0; i < 4; i++)
        t[ty + i * 8][tx] = x[boff + (size_t)(c0 + ty + i * 8) * kN + n0 + tx];
    __syncthreads();
    const int c = c0 + tx;
    const float2 st = stats[bz * kG + (c >> 4)];
    const float sc = scale[c] * st.y;
    const float bi = bias[c] - st.x * sc;
    #pragma unroll
    for (int i = 0; i < 4; i++)
        dst[boff + (size_t)(n0 + ty + i * 8) * kC + c] =
            __float2bfloat16_rn(t[tx][ty + i * 8] * sc + bi);
}

// ---------------------------------------------------------------------------
// Merged setup: weight cvt (1M elems) + bias concat + rowsum zero, one launch.
// ---------------------------------------------------------------------------
__global__ __launch_bounds__(256) void setup_kernel(
    const float* __restrict__ wq, const float* __restrict__ wk,
    const float* __restrict__ wv, const float* __restrict__ wo,
    __nv_bfloat16* __restrict__ wdst,
    const float* __restrict__ bq, const float* __restrict__ bk,
    float* __restrict__ bqk, float* __restrict__ rowsum)
{
    const int i = blockIdx.x * 256 + threadIdx.x;     // < 1048576
    const int sel = i >> 18;
    const int off = i & 0x3FFFF;
    const float* src = (sel == 0) ? wq : (sel == 1) ? wk : (sel == 2) ? wv : wo;
    wdst[i] = __float2bfloat16_rn(src[off]);
    if (i < 1024) bqk[i] = (i < 512) ? bq[i] : bk[i - 512];
    if (i < kB * kN) rowsum[i] = 0.f;
}

// ---------------------------------------------------------------------------
extern "C" void kernel_launch(void* const* d_in, const int* in_sizes, int n_in,
                              void* d_out, int out_size) {
    const float* x  = (const float*)d_in[0];
    const float* gs = (const float*)d_in[1];
    const float* gb = (const float*)d_in[2];
    const float* wq = (const float*)d_in[3];
    const float* bq = (const float*)d_in[4];
    const float* wk = (const float*)d_in[5];
    const float* bk = (const float*)d_in[6];
    const float* wv = (const float*)d_in[7];
    const float* bv = (const float*)d_in[8];
    const float* wo = (const float*)d_in[9];
    const float* bo = (const float*)d_in[10];
    float* out = (float*)d_out;

    __nv_bfloat16 *hnT, *qkb, *v, *oT, *probs, *wr;
    float *bqk, *rowsum;
    float2* stats;
    cudaGetSymbolAddress((void**)&hnT,    g_hnT);
    cudaGetSymbolAddress((void**)&qkb,    g_qk);
    cudaGetSymbolAddress((void**)&v,      g_v);
    cudaGetSymbolAddress((void**)&oT,     g_oT);
    cudaGetSymbolAddress((void**)&probs,  g_s);
    cudaGetSymbolAddress((void**)&wr,     g_wr);
    cudaGetSymbolAddress((void**)&bqk,    g_bqk);
    cudaGetSymbolAddress((void**)&stats,  g_stats);
    cudaGetSymbolAddress((void**)&rowsum, g_rowsum);
    __nv_bfloat16* wvr = wr + 2 * (size_t)kC * kC;
    __nv_bfloat16* wor = wr + 3 * (size_t)kC * kC;

    cudaFuncSetAttribute(
        (const void*)mma_gemm<__nv_bfloat16, true,  false, false, false, false>,
        cudaFuncAttributeMaxDynamicSharedMemorySize, kSmemBytes);
    cudaFuncSetAttribute(
        (const void*)mma_gemm<__nv_bfloat16, false, true,  false, false, false>,
        cudaFuncAttributeMaxDynamicSharedMemorySize, kSmemBytes);
    cudaFuncSetAttribute(
        (const void*)mma_gemm<__nv_bfloat16, false, false, false, true,  false>,
        cudaFuncAttributeMaxDynamicSharedMemorySize, kSmemBytes);
    cudaFuncSetAttribute(
        (const void*)mma_gemm<__nv_bfloat16, false, false, false, false, true>,
        cudaFuncAttributeMaxDynamicSharedMemorySize, kSmemBytes);
    cudaFuncSetAttribute(
        (const void*)mma_gemm<float,         false, true,  true,  false, false>,
        cudaFuncAttributeMaxDynamicSharedMemorySize, kSmemBytes);

    setup_kernel<<<4096, 256>>>(wq, wk, wv, wo, wr, bq, bk, bqk, rowsum);
    gn_stats_kernel<<<kB * kG, 256>>>(x, stats);
    transnorm_kernel<<<dim3(kN / 32, kC / 32, kB), 256>>>(x, stats, gs, gb, hnT);

    // Fused Q|K projection: [4096, 1024] = hn_T @ [wq;wk]^T + [bq;bk]
    const dim3 gQKp(1024 / 128, kN / 128, kB);
    mma_gemm<__nv_bfloat16, true, false, false, false, false>
        <<<gQKp, 256, kSmemBytes>>>(
        hnT, kC, kCN, wr, kC, 0, qkb, 1024, (size_t)kN * 1024,
        kC, 1.f, bqk, nullptr, 0, nullptr, 0);

    // V: [c, spatial]
    const dim3 gV(kN / 128, kC / 128, kB);
    mma_gemm<__nv_bfloat16, false, true, false, false, false>
        <<<gV, 256, kSmemBytes>>>(
        wvr, kC, 0, hnT, kC, kCN, v, kN, kCN, kC, 1.f, bv, nullptr, 0,
        nullptr, 0);

    // probs[i,j] = exp2((q.k) * log2e / sqrt(C)) -> bf16, rowsum += partials
    const dim3 gS(kN / 128, kN / 128, kB);
    mma_gemm<__nv_bfloat16, false, false, false, true, false>
        <<<gS, 256, kSmemBytes>>>(
        qkb, 1024, (size_t)kN * 1024, qkb + 512, 1024, (size_t)kN * 1024,
        probs, kN, kNN, kC,
        0.044194173824159216f * 1.4426950408889634f, nullptr, nullptr, 0,
        rowsum, kN);

    // oT[i,c] = (sum_j P[i,j] * v[c,j]) / rowsum[i]
    const dim3 gO(kC / 128, kN / 128, kB);
    mma_gemm<__nv_bfloat16, false, false, false, false, true>
        <<<gO, 256, kSmemBytes>>>(
        probs, kN, kNN, v, kN, kCN, oT, kC, kCN, kN, 1.f, nullptr, nullptr, 0,
        rowsum, kN);

    // out = W_o @ oT^T + bo + x
    mma_gemm<float, false, true, true, false, false><<<gV, 256, kSmemBytes>>>(
        wor, kC, 0, oT, kC, kCN, out, kN, kCN, kC, 1.f, bo, x, kCN,
        nullptr, 0);
}